// round 10
// baseline (speedup 1.0000x reference)
#include <cuda_runtime.h>
#include <cstdint>

// ============================================================================
// RPN GT matcher — bit-exact JAX Threefry (partitionable), integer-monotone
// gumbel/uniform ordering, GT spatial binning.
// R9: revert to SBT=2 (R6 config; SBT>=4 regresses ~35%, twice confirmed);
// add software-pipelined prefetch of the neg-list index so the L2 load
// latency hides under the Threefry chains; keep fused-mask LOP3.
// ============================================================================

#define N_ANCH 262144
#define NB 4
#define NG 64
#define TFG 153          // TARGET_FG
#define SB 512           // SAMPLE_BATCH
#define SBT 2            // samples per block in k_sample (empirical optimum)
#define FULLMASK 0xFFFFFFFFu
#define NCELL 256        // 16x16 cells of 64px

struct Keys { uint32_t kp0[NB], kp1[NB], kn0[NB], kn1[NB]; uint32_t one; };

__host__ __device__ __forceinline__ uint32_t rotl32(uint32_t x, int r) {
#ifdef __CUDA_ARCH__
    return __funnelshift_l(x, x, r);
#else
    return (x << r) | (x >> (32 - r));
#endif
}

// Threefry-2x32, 20 rounds, exactly as jax._src.prng.threefry2x32 (host/ref)
__host__ __device__ __forceinline__ void threefry(uint32_t k0, uint32_t k1,
                                                  uint32_t x0, uint32_t x1,
                                                  uint32_t& o0, uint32_t& o1) {
    uint32_t ks2 = k0 ^ k1 ^ 0x1BD11BDAu;
    x0 += k0; x1 += k1;
#define TFR(r) { x0 += x1; x1 = rotl32(x1, r); x1 ^= x0; }
    TFR(13) TFR(15) TFR(26) TFR(6)
    x0 += k1;  x1 += ks2 + 1u;
    TFR(17) TFR(29) TFR(16) TFR(24)
    x0 += ks2; x1 += k0 + 2u;
    TFR(13) TFR(15) TFR(26) TFR(6)
    x0 += k0;  x1 += k1 + 3u;
    TFR(17) TFR(29) TFR(16) TFR(24)
    x0 += k1;  x1 += ks2 + 4u;
    TFR(13) TFR(15) TFR(26) TFR(6)
    x0 += ks2; x1 += k0 + 5u;
#undef TFR
    o0 = x0; o1 = x1;
}

// Threefry with adds expressed as a*one+b (one==1 at runtime, opaque) so
// ptxas emits IMAD on the fma pipe; SHF/LOP3 stay on alu (their floor).
// x1 must arrive pre-added with k1 (counter x0 = 0).
// Returns (o0 ^ o1) & 0xFFFFFE00 — mask fused into the final LOP3.
// ((masked) >> 9 equals (unmasked) >> 9.)
__device__ __forceinline__ uint32_t tf_imad(uint32_t k0, uint32_t k1,
                                            uint32_t ks2,
                                            uint32_t kA, uint32_t kB,
                                            uint32_t kC, uint32_t kD,
                                            uint32_t kE,
                                            uint32_t x1, uint32_t one) {
    uint32_t x0 = k0;
#define AD(a, b) ((a) * one + (b))
#define RR(r) { x0 = AD(x0, x1); x1 = rotl32(x1, (r)); x1 ^= x0; }
    RR(13) RR(15) RR(26) RR(6)
    x0 = AD(x0, k1);  x1 = AD(x1, kA);
    RR(17) RR(29) RR(16) RR(24)
    x0 = AD(x0, ks2); x1 = AD(x1, kB);
    RR(13) RR(15) RR(26) RR(6)
    x0 = AD(x0, k0);  x1 = AD(x1, kC);
    RR(17) RR(29) RR(16) RR(24)
    x0 = AD(x0, k1);  x1 = AD(x1, kD);
    RR(13) RR(15) RR(26) RR(6)
    return (AD(x0, ks2) ^ AD(x1, kE)) & 0xFFFFFE00u;
#undef AD
#undef RR
}

// ---------------------------------------------------------------------------
__device__ __forceinline__ float f_area(float4 v) {
    return __fmul_rn(__fadd_rn(__fsub_rn(v.z, v.x), 1.0f),
                     __fadd_rn(__fsub_rn(v.w, v.y), 1.0f));
}

// ---------------------------------------------------------------------------
// Scratch (static __device__ — no allocation allowed)
// ---------------------------------------------------------------------------
__device__ uint32_t d_g2a[NB][NG];
__device__ uint8_t  d_aidx[NB][N_ANCH];
__device__ int8_t   d_lab[NB][N_ANCH];
__device__ unsigned long long d_poskey[NB][N_ANCH];
__device__ int      d_negl[NB][N_ANCH];
__device__ int      d_poscnt[NB], d_negcnt[NB], d_tbg[NB], d_dosamp[NB];
__device__ __align__(16) uint8_t d_cellgt[NB][NCELL][64];
__device__ int      d_cellcnt[NB][NCELL];

// ---------------------------------------------------------------------------
__global__ __launch_bounds__(256) void k_init() {
    int t = threadIdx.x;
    if (t < NB * NG) ((uint32_t*)d_g2a)[t] = 0;
    if (t < NB) { d_poscnt[t] = 0; d_negcnt[t] = 0; }
}

// Bin valid GTs into 16x16 cells keyed by anchor (x1,y1) position.
__global__ __launch_bounds__(256) void k_bins(const float4* __restrict__ gt,
                                              const int* __restrict__ gti) {
    int t = blockIdx.x * 256 + threadIdx.x;
    int b = t >> 8, c = t & 255;
    int cx = c & 15, cy = c >> 4;
    float x0 = cx * 64.0f, y0 = cy * 64.0f;
    int n = 0;
    for (int g = 0; g < NG; g++) {
        if (gti[b * NG + g] != 0) continue;
        float4 gb = gt[b * NG + g];
        bool ox = (gb.z >= x0 - 1.5f) && (gb.x <= x0 + 226.5f);
        bool oy = (gb.w >= y0 - 1.5f) && (gb.y <= y0 + 226.5f);
        if (ox && oy) d_cellgt[b][c][n++] = (uint8_t)g;
    }
    d_cellcnt[b][c] = n;
}

// Pass 1: per-gt column max (binned; divide only when inter>0).
__global__ __launch_bounds__(256) void k_colmax(const float4* __restrict__ boxes,
                                                const float4* __restrict__ gt,
                                                const float* __restrict__ imi) {
    __shared__ float4 sgt[NG];
    __shared__ float  sga[NG];
    __shared__ uint32_t sg2a[NG];
    __shared__ uint8_t slist[NCELL * 64];
    __shared__ int     scnt[NCELL];
    int b = blockIdx.y, tid = threadIdx.x;
    if (tid < NG) {
        sg2a[tid] = 0;
        float4 g = gt[b * NG + tid];
        sgt[tid] = g; sga[tid] = f_area(g);
    }
    {
        const int4* src = (const int4*)d_cellgt[b];
        int4* dst = (int4*)slist;
        for (int k = tid; k < NCELL * 64 / 16; k += 256) dst[k] = src[k];
        scnt[tid] = d_cellcnt[b][tid];
    }
    __syncthreads();
    float limw = __fadd_rn(imi[b * 3 + 1], 1.0f);
    float limh = __fadd_rn(imi[b * 3 + 0], 1.0f);
    int base = blockIdx.x * 1024 + tid;
    for (int it = 0; it < 4; it++) {
        int i = base + it * 256;
        float4 a = boxes[i];
        bool inside = (a.x >= 0.0f) && (a.y >= 0.0f) && (a.z < limw) && (a.w < limh);
        if (!inside) continue;
        float aa = f_area(a);
        int cx = min((int)(a.x * (1.0f / 64.0f)), 15);
        int cy = min((int)(a.y * (1.0f / 64.0f)), 15);
        int c = cy * 16 + cx;
        int n = scnt[c];
        const uint8_t* lp = &slist[c * 64];
        for (int j = 0; j < n; j++) {
            int g = lp[j];
            float4 gb = sgt[g];
            float wx = __fadd_rn(__fsub_rn(fminf(a.z, gb.z), fmaxf(a.x, gb.x)), 1.0f);
            float wy = __fadd_rn(__fsub_rn(fminf(a.w, gb.w), fmaxf(a.y, gb.y)), 1.0f);
            wx = fmaxf(wx, 0.0f); wy = fmaxf(wy, 0.0f);
            float inter = __fmul_rn(wx, wy);
            if (inter > 0.0f) {
                float v = __fdiv_rn(inter, __fsub_rn(__fadd_rn(aa, sga[g]), inter));
                atomicMax(&sg2a[g], __float_as_uint(v));
            }
        }
    }
    __syncthreads();
    if (tid < NG && sg2a[tid]) atomicMax(&d_g2a[b][tid], sg2a[tid]);
}

// Pass 2: per-anchor match + classification + compaction + priority keys.
__global__ __launch_bounds__(256) void k_match(const float4* __restrict__ boxes,
                                               const float4* __restrict__ gt,
                                               const float* __restrict__ imi,
                                               Keys keys) {
    __shared__ float4 sgt[NG];
    __shared__ float  sga[NG], sg2af[NG];
    __shared__ uint8_t slist[NCELL * 64];
    __shared__ int     scnt[NCELL];
    int b = blockIdx.y, tid = threadIdx.x, lane = tid & 31;
    if (tid < NG) {
        float4 g = gt[b * NG + tid];
        sgt[tid] = g; sga[tid] = f_area(g);
        float f = __uint_as_float(d_g2a[b][tid]);
        sg2af[tid] = (f == 0.0f) ? 1.0f : f;
    }
    {
        const int4* src = (const int4*)d_cellgt[b];
        int4* dst = (int4*)slist;
        for (int k = tid; k < NCELL * 64 / 16; k += 256) dst[k] = src[k];
        scnt[tid] = d_cellcnt[b][tid];
    }
    __syncthreads();
    uint32_t pk0 = keys.kp0[b], pk1 = keys.kp1[b];
    uint32_t pks2 = pk0 ^ pk1 ^ 0x1BD11BDAu;
    float limw = __fadd_rn(imi[b * 3 + 1], 1.0f);
    float limh = __fadd_rn(imi[b * 3 + 0], 1.0f);
    int base = blockIdx.x * 1024 + tid;
    for (int it = 0; it < 4; it++) {
        int i = base + it * 256;
        float4 a = boxes[i];
        bool inside = (a.x >= 0.0f) && (a.y >= 0.0f) && (a.z < limw) && (a.w < limh);
        float best = 0.0f; int bidx = 0; bool wm = false;
        if (inside) {
            float aa = f_area(a);
            int cx = min((int)(a.x * (1.0f / 64.0f)), 15);
            int cy = min((int)(a.y * (1.0f / 64.0f)), 15);
            int c = cy * 16 + cx;
            int n = scnt[c];
            const uint8_t* lp = &slist[c * 64];
            for (int j = 0; j < n; j++) {
                int g = lp[j];
                float4 gb = sgt[g];
                float wx = __fadd_rn(__fsub_rn(fminf(a.z, gb.z), fmaxf(a.x, gb.x)), 1.0f);
                float wy = __fadd_rn(__fsub_rn(fminf(a.w, gb.w), fmaxf(a.y, gb.y)), 1.0f);
                wx = fmaxf(wx, 0.0f); wy = fmaxf(wy, 0.0f);
                float inter = __fmul_rn(wx, wy);
                if (inter > 0.0f) {
                    float v = __fdiv_rn(inter, __fsub_rn(__fadd_rn(aa, sga[g]), inter));
                    if (v > best) { best = v; bidx = g; }
                    wm |= (v == sg2af[g]);
                }
            }
        }
        bool pos = inside && (wm || best >= 0.5f);
        bool neg = inside && (best < 0.3f);
        d_aidx[b][i] = (uint8_t)bidx;
        d_lab[b][i] = -1;

        unsigned mneg = __ballot_sync(FULLMASK, neg);
        if (mneg) {
            int leader = __ffs(mneg) - 1, basek = 0;
            if (lane == leader) basek = atomicAdd(&d_negcnt[b], __popc(mneg));
            basek = __shfl_sync(FULLMASK, basek, leader);
            if (neg) d_negl[b][basek + __popc(mneg & ((1u << lane) - 1))] = i;
        }
        unsigned mpos = __ballot_sync(FULLMASK, pos);
        if (mpos) {
            int leader = __ffs(mpos) - 1, basek = 0;
            if (lane == leader) basek = atomicAdd(&d_poscnt[b], __popc(mpos));
            basek = __shfl_sync(FULLMASK, basek, leader);
            if (pos) {
                uint32_t bits = tf_imad(pk0, pk1, pks2,
                                        pks2 + 1u, pk0 + 2u, pk1 + 3u,
                                        pks2 + 4u, pk0 + 5u,
                                        (uint32_t)i + pk1, keys.one);
                uint32_t m23 = bits >> 9;  // masked low bits shift out anyway
                unsigned long long key =
                    ((unsigned long long)m23 << 18) | (unsigned)(N_ANCH - 1 - i);
                d_poskey[b][basek + __popc(mpos & ((1u << lane) - 1))] = key;
            }
        }
    }
}

// Pass 3: O(P) top-TFG selection via histogram + exact rank in threshold bin.
#define NBIN 4096
#define BINCAP 2048
__global__ __launch_bounds__(1024) void k_select() {
    __shared__ uint32_t hist[NBIN];
    __shared__ unsigned long long binkeys[BINCAP];
    __shared__ int s_thr, s_need, s_cnt;
    int b = blockIdx.x, tid = threadIdx.x;
    int P = d_poscnt[b];
    if (tid == 0) {
        int nf = min(P, TFG);
        int tb = SB - nf;
        d_tbg[b] = tb;
        d_dosamp[b] = (d_negcnt[b] > tb) ? 1 : 0;
    }
    if (P <= TFG) {
        for (int e = tid; e < P; e += 1024) {
            unsigned long long k = d_poskey[b][e];
            d_lab[b][N_ANCH - 1 - (int)(k & 0x3FFFFu)] = 1;
        }
        return;
    }
    for (int i = tid; i < NBIN; i += 1024) hist[i] = 0;
    __syncthreads();
    for (int e = tid; e < P; e += 1024)
        atomicAdd(&hist[(int)(d_poskey[b][e] >> 29)], 1u);
    __syncthreads();
    if (tid == 0) {
        int cum = 0, t = 0, need = TFG;
        for (int bin = NBIN - 1; bin >= 0; bin--) {
            int c = (int)hist[bin];
            if (cum + c >= TFG) { t = bin; need = TFG - cum; break; }
            cum += c;
        }
        s_thr = t; s_need = need; s_cnt = 0;
    }
    __syncthreads();
    int t = s_thr, need = s_need;
    for (int e = tid; e < P; e += 1024) {
        unsigned long long k = d_poskey[b][e];
        int bin = (int)(k >> 29);
        if (bin > t) {
            d_lab[b][N_ANCH - 1 - (int)(k & 0x3FFFFu)] = 1;
        } else if (bin == t) {
            int p = atomicAdd(&s_cnt, 1);
            if (p < BINCAP) binkeys[p] = k;
        }
    }
    __syncthreads();
    int C = min(s_cnt, BINCAP);
    for (int e = tid; e < C; e += 1024) {
        unsigned long long k = binkeys[e];
        int c = 0;
        for (int j = 0; j < C; j++) c += (binkeys[j] > k);
        if (c < need) d_lab[b][N_ANCH - 1 - (int)(k & 0x3FFFFu)] = 1;
    }
}

// Pass 4: categorical sampling. SBT=2 samples per block; software-pipelined
// index prefetch (next LDG issued before the two ~240-cyc Threefry chains);
// running masked-mantissa max with rare tie branch; exact smallest-index
// tie-break through reductions (order-independent — required because negl
// ordering from atomics is nondeterministic).
__global__ __launch_bounds__(256) void k_sample(Keys keys) {
    __shared__ uint32_t redv[SBT][8];
    __shared__ uint32_t redi[SBT][8];
    int b = blockIdx.y, tid = threadIdx.x;
    int s0 = blockIdx.x * SBT;
    int tbg = d_tbg[b];
    if (!d_dosamp[b] || s0 >= tbg) return;
    int M = d_negcnt[b];
    uint32_t one = keys.one;
    uint32_t k0 = keys.kn0[b], k1 = keys.kn1[b];
    uint32_t ks2 = k0 ^ k1 ^ 0x1BD11BDAu;
    uint32_t kA = ks2 + 1u, kB = k0 + 2u, kC = k1 + 3u, kD = ks2 + 4u, kE = k0 + 5u;
    uint32_t h0 = (uint32_t)s0 * (uint32_t)N_ANCH + k1;   // x1 base, sample s0
    uint32_t h1 = h0 + (uint32_t)N_ANCH;                  // sample s0+1

    uint32_t bv0 = 0, bi0 = 0xFFFFFFFFu, bv1 = 0, bi1 = 0xFFFFFFFFu;
    const int* negl = d_negl[b];

    int t = tid;
    uint32_t i_next = (t < M) ? (uint32_t)__ldg(&negl[t]) : 0u;
    while (t < M) {
        uint32_t i = i_next;
        int t2 = t + 256;
        if (t2 < M) i_next = (uint32_t)__ldg(&negl[t2]);  // prefetch ahead
        uint32_t r0 = tf_imad(k0, k1, ks2, kA, kB, kC, kD, kE, h0 + i, one);
        if (r0 >= bv0) { if (r0 > bv0 || i < bi0) { bv0 = r0; bi0 = i; } }
        uint32_t r1 = tf_imad(k0, k1, ks2, kA, kB, kC, kD, kE, h1 + i, one);
        if (r1 >= bv1) { if (r1 > bv1 || i < bi1) { bv1 = r1; bi1 = i; } }
        t = t2;
    }
    int lane = tid & 31, wid = tid >> 5;
    #pragma unroll
    for (int off = 16; off; off >>= 1) {
        uint32_t ov = __shfl_xor_sync(FULLMASK, bv0, off);
        uint32_t oi = __shfl_xor_sync(FULLMASK, bi0, off);
        if (ov > bv0 || (ov == bv0 && oi < bi0)) { bv0 = ov; bi0 = oi; }
        ov = __shfl_xor_sync(FULLMASK, bv1, off);
        oi = __shfl_xor_sync(FULLMASK, bi1, off);
        if (ov > bv1 || (ov == bv1 && oi < bi1)) { bv1 = ov; bi1 = oi; }
    }
    if (lane == 0) {
        redv[0][wid] = bv0; redi[0][wid] = bi0;
        redv[1][wid] = bv1; redi[1][wid] = bi1;
    }
    __syncthreads();
    if (tid < SBT) {
        uint32_t v = redv[tid][0], i = redi[tid][0];
        #pragma unroll
        for (int w = 1; w < 8; w++) {
            uint32_t ov = redv[tid][w], oi = redi[tid][w];
            if (ov > v || (ov == v && oi < i)) { v = ov; i = oi; }
        }
        if (s0 + tid < tbg) d_lab[b][i] = 0;
    }
}

// Pass 5: emit labels (as float) + bbox regression targets.
__global__ __launch_bounds__(256) void k_out(const float4* __restrict__ boxes,
                                             const float4* __restrict__ gt,
                                             float* __restrict__ outL,
                                             float4* __restrict__ outB) {
    __shared__ float4 sgt[NG];
    int b = blockIdx.y, tid = threadIdx.x;
    if (tid < NG) sgt[tid] = gt[b * NG + tid];
    __syncthreads();
    int i = blockIdx.x * 256 + tid;
    int lab = d_lab[b][i];
    outL[b * N_ANCH + i] = (float)lab;
    float4 t = make_float4(0.f, 0.f, 0.f, 0.f);
    if (lab > 0) {
        float4 a = boxes[i];
        float4 g = sgt[d_aidx[b][i]];
        float ew = a.z - a.x + 1.0f, eh = a.w - a.y + 1.0f;
        float ecx = a.x + 0.5f * ew, ecy = a.y + 0.5f * eh;
        float gw = g.z - g.x + 1.0f, gh = g.w - g.y + 1.0f;
        float gcx = g.x + 0.5f * gw, gcy = g.y + 0.5f * gh;
        t.x = (gcx - ecx) / ew;
        t.y = (gcy - ecy) / eh;
        t.z = logf(gw / ew);
        t.w = logf(gh / eh);
    }
    outB[b * N_ANCH + i] = t;
}

// ---------------------------------------------------------------------------
extern "C" void kernel_launch(void* const* d_in, const int* in_sizes, int n_in,
                              void* d_out, int out_size) {
    const float4* boxes = (const float4*)d_in[0];
    const float4* gt    = (const float4*)d_in[1];
    const int*    gti   = (const int*)d_in[3];   // gt_ignore_labels
    const float*  imi   = (const float*)d_in[4]; // im_info
    float* out = (float*)d_out;

    // Host-side key derivation (jax.random.key(42), partitionable threefry).
    Keys keys;
    keys.one = 1u;
    for (int b = 0; b < NB; b++) {
        uint32_t kb0, kb1;
        threefry(0u, 42u, 0u, (uint32_t)b, kb0, kb1);         // split(key,B)[b]
        threefry(kb0, kb1, 0u, 0u, keys.kp0[b], keys.kp1[b]); // kp
        threefry(kb0, kb1, 0u, 1u, keys.kn0[b], keys.kn1[b]); // kn
    }

    k_init<<<1, 256>>>();
    k_bins<<<NB, 256>>>(gt, gti);
    k_colmax<<<dim3(N_ANCH / 1024, NB), 256>>>(boxes, gt, imi);
    k_match<<<dim3(N_ANCH / 1024, NB), 256>>>(boxes, gt, imi, keys);
    k_select<<<NB, 1024>>>();
    k_sample<<<dim3(SB / SBT, NB), 256>>>(keys);
    k_out<<<dim3(N_ANCH / 256, NB), 256>>>(boxes, gt, out,
                                           (float4*)(out + NB * N_ANCH));
}

// round 11
// speedup vs baseline: 1.5435x; 1.5435x over previous
#include <cuda_runtime.h>
#include <cstdint>

// ============================================================================
// RPN GT matcher — bit-exact JAX Threefry (partitionable), integer-monotone
// gumbel/uniform ordering, GT spatial binning.
// R10: base = R6 champion (1000us). ONLY change: 5 of 20 rotations (r=13,17)
// computed as x1*2^r lo/hi (IMAD + IMAD.HI, fma pipe, single-reg dests) with
// (lo|hi)^x0 fused in one LOP3 — equalizes alu/fma at 40/40 per threefry.
// Inner sampler loop structure untouched (R9 lesson). Mask fused in out-LOP3.
// ============================================================================

#define N_ANCH 262144
#define NB 4
#define NG 64
#define TFG 153          // TARGET_FG
#define SB 512           // SAMPLE_BATCH
#define SBT 2            // samples per block in k_sample (empirical optimum)
#define FULLMASK 0xFFFFFFFFu
#define NCELL 256        // 16x16 cells of 64px

struct Keys {
    uint32_t kp0[NB], kp1[NB], kn0[NB], kn1[NB];
    uint32_t one;        // ==1       (opaque: IMAD adds)
    uint32_t m13, m17;   // ==1<<13, ==1<<17 (opaque: IMAD/IMAD.HI rotations)
};

__host__ __device__ __forceinline__ uint32_t rotl32(uint32_t x, int r) {
#ifdef __CUDA_ARCH__
    return __funnelshift_l(x, x, r);
#else
    return (x << r) | (x >> (32 - r));
#endif
}

// Threefry-2x32, 20 rounds, exactly as jax._src.prng.threefry2x32 (host/ref)
__host__ __device__ __forceinline__ void threefry(uint32_t k0, uint32_t k1,
                                                  uint32_t x0, uint32_t x1,
                                                  uint32_t& o0, uint32_t& o1) {
    uint32_t ks2 = k0 ^ k1 ^ 0x1BD11BDAu;
    x0 += k0; x1 += k1;
#define TFR(r) { x0 += x1; x1 = rotl32(x1, r); x1 ^= x0; }
    TFR(13) TFR(15) TFR(26) TFR(6)
    x0 += k1;  x1 += ks2 + 1u;
    TFR(17) TFR(29) TFR(16) TFR(24)
    x0 += ks2; x1 += k0 + 2u;
    TFR(13) TFR(15) TFR(26) TFR(6)
    x0 += k0;  x1 += k1 + 3u;
    TFR(17) TFR(29) TFR(16) TFR(24)
    x0 += k1;  x1 += ks2 + 4u;
    TFR(13) TFR(15) TFR(26) TFR(6)
    x0 += ks2; x1 += k0 + 5u;
#undef TFR
    o0 = x0; o1 = x1;
}

// Pipe-balanced Threefry:
//  - adds as a*one+b (IMAD, fma pipe; one==1 opaque)
//  - rotations r=13 (x3) and r=17 (x2) as lo=x1*m / hi=umulhi(x1,m)
//    (IMAD + IMAD.HI, fma pipe, single-register results) with the combine
//    and xor fused into ONE LOP3: (lo|hi)^x0. Other 15 rotations stay
//    SHF+LOP3 on alu. Net per threefry: ~40 alu / ~40 fma (was 45/30).
// x1 must arrive pre-added with k1 (counter x0 = 0).
// Returns (o0 ^ o1) & 0xFFFFFE00 (mask fused; (masked)>>9 == (raw)>>9).
__device__ __forceinline__ uint32_t tf_bal(uint32_t k0, uint32_t k1,
                                           uint32_t ks2,
                                           uint32_t kA, uint32_t kB,
                                           uint32_t kC, uint32_t kD,
                                           uint32_t kE,
                                           uint32_t x1, uint32_t one,
                                           uint32_t m13, uint32_t m17) {
    uint32_t x0 = k0;
#define AD(a, b) ((a) * one + (b))
#define RR(r) { x0 = AD(x0, x1); x1 = rotl32(x1, (r)); x1 ^= x0; }
#define RH(m) { x0 = AD(x0, x1); \
                uint32_t lo_ = x1 * (m); \
                uint32_t hi_ = __umulhi(x1, (m)); \
                x1 = (lo_ | hi_) ^ x0; }
    RH(m13) RR(15) RR(26) RR(6)
    x0 = AD(x0, k1);  x1 = AD(x1, kA);
    RH(m17) RR(29) RR(16) RR(24)
    x0 = AD(x0, ks2); x1 = AD(x1, kB);
    RH(m13) RR(15) RR(26) RR(6)
    x0 = AD(x0, k0);  x1 = AD(x1, kC);
    RH(m17) RR(29) RR(16) RR(24)
    x0 = AD(x0, k1);  x1 = AD(x1, kD);
    RH(m13) RR(15) RR(26) RR(6)
    return (AD(x0, ks2) ^ AD(x1, kE)) & 0xFFFFFE00u;
#undef AD
#undef RR
#undef RH
}

// ---------------------------------------------------------------------------
__device__ __forceinline__ float f_area(float4 v) {
    return __fmul_rn(__fadd_rn(__fsub_rn(v.z, v.x), 1.0f),
                     __fadd_rn(__fsub_rn(v.w, v.y), 1.0f));
}

// ---------------------------------------------------------------------------
// Scratch (static __device__ — no allocation allowed)
// ---------------------------------------------------------------------------
__device__ uint32_t d_g2a[NB][NG];
__device__ uint8_t  d_aidx[NB][N_ANCH];
__device__ int8_t   d_lab[NB][N_ANCH];
__device__ unsigned long long d_poskey[NB][N_ANCH];
__device__ int      d_negl[NB][N_ANCH];
__device__ int      d_poscnt[NB], d_negcnt[NB], d_tbg[NB], d_dosamp[NB];
__device__ __align__(16) uint8_t d_cellgt[NB][NCELL][64];
__device__ int      d_cellcnt[NB][NCELL];

// ---------------------------------------------------------------------------
__global__ __launch_bounds__(256) void k_init() {
    int t = threadIdx.x;
    if (t < NB * NG) ((uint32_t*)d_g2a)[t] = 0;
    if (t < NB) { d_poscnt[t] = 0; d_negcnt[t] = 0; }
}

// Bin valid GTs into 16x16 cells keyed by anchor (x1,y1) position.
__global__ __launch_bounds__(256) void k_bins(const float4* __restrict__ gt,
                                              const int* __restrict__ gti) {
    int t = blockIdx.x * 256 + threadIdx.x;
    int b = t >> 8, c = t & 255;
    int cx = c & 15, cy = c >> 4;
    float x0 = cx * 64.0f, y0 = cy * 64.0f;
    int n = 0;
    for (int g = 0; g < NG; g++) {
        if (gti[b * NG + g] != 0) continue;
        float4 gb = gt[b * NG + g];
        bool ox = (gb.z >= x0 - 1.5f) && (gb.x <= x0 + 226.5f);
        bool oy = (gb.w >= y0 - 1.5f) && (gb.y <= y0 + 226.5f);
        if (ox && oy) d_cellgt[b][c][n++] = (uint8_t)g;
    }
    d_cellcnt[b][c] = n;
}

// Pass 1: per-gt column max (binned; divide only when inter>0).
__global__ __launch_bounds__(256) void k_colmax(const float4* __restrict__ boxes,
                                                const float4* __restrict__ gt,
                                                const float* __restrict__ imi) {
    __shared__ float4 sgt[NG];
    __shared__ float  sga[NG];
    __shared__ uint32_t sg2a[NG];
    __shared__ uint8_t slist[NCELL * 64];
    __shared__ int     scnt[NCELL];
    int b = blockIdx.y, tid = threadIdx.x;
    if (tid < NG) {
        sg2a[tid] = 0;
        float4 g = gt[b * NG + tid];
        sgt[tid] = g; sga[tid] = f_area(g);
    }
    {
        const int4* src = (const int4*)d_cellgt[b];
        int4* dst = (int4*)slist;
        for (int k = tid; k < NCELL * 64 / 16; k += 256) dst[k] = src[k];
        scnt[tid] = d_cellcnt[b][tid];
    }
    __syncthreads();
    float limw = __fadd_rn(imi[b * 3 + 1], 1.0f);
    float limh = __fadd_rn(imi[b * 3 + 0], 1.0f);
    int base = blockIdx.x * 1024 + tid;
    for (int it = 0; it < 4; it++) {
        int i = base + it * 256;
        float4 a = boxes[i];
        bool inside = (a.x >= 0.0f) && (a.y >= 0.0f) && (a.z < limw) && (a.w < limh);
        if (!inside) continue;
        float aa = f_area(a);
        int cx = min((int)(a.x * (1.0f / 64.0f)), 15);
        int cy = min((int)(a.y * (1.0f / 64.0f)), 15);
        int c = cy * 16 + cx;
        int n = scnt[c];
        const uint8_t* lp = &slist[c * 64];
        for (int j = 0; j < n; j++) {
            int g = lp[j];
            float4 gb = sgt[g];
            float wx = __fadd_rn(__fsub_rn(fminf(a.z, gb.z), fmaxf(a.x, gb.x)), 1.0f);
            float wy = __fadd_rn(__fsub_rn(fminf(a.w, gb.w), fmaxf(a.y, gb.y)), 1.0f);
            wx = fmaxf(wx, 0.0f); wy = fmaxf(wy, 0.0f);
            float inter = __fmul_rn(wx, wy);
            if (inter > 0.0f) {
                float v = __fdiv_rn(inter, __fsub_rn(__fadd_rn(aa, sga[g]), inter));
                atomicMax(&sg2a[g], __float_as_uint(v));
            }
        }
    }
    __syncthreads();
    if (tid < NG && sg2a[tid]) atomicMax(&d_g2a[b][tid], sg2a[tid]);
}

// Pass 2: per-anchor match + classification + compaction + priority keys.
__global__ __launch_bounds__(256) void k_match(const float4* __restrict__ boxes,
                                               const float4* __restrict__ gt,
                                               const float* __restrict__ imi,
                                               Keys keys) {
    __shared__ float4 sgt[NG];
    __shared__ float  sga[NG], sg2af[NG];
    __shared__ uint8_t slist[NCELL * 64];
    __shared__ int     scnt[NCELL];
    int b = blockIdx.y, tid = threadIdx.x, lane = tid & 31;
    if (tid < NG) {
        float4 g = gt[b * NG + tid];
        sgt[tid] = g; sga[tid] = f_area(g);
        float f = __uint_as_float(d_g2a[b][tid]);
        sg2af[tid] = (f == 0.0f) ? 1.0f : f;
    }
    {
        const int4* src = (const int4*)d_cellgt[b];
        int4* dst = (int4*)slist;
        for (int k = tid; k < NCELL * 64 / 16; k += 256) dst[k] = src[k];
        scnt[tid] = d_cellcnt[b][tid];
    }
    __syncthreads();
    uint32_t pk0 = keys.kp0[b], pk1 = keys.kp1[b];
    uint32_t pks2 = pk0 ^ pk1 ^ 0x1BD11BDAu;
    float limw = __fadd_rn(imi[b * 3 + 1], 1.0f);
    float limh = __fadd_rn(imi[b * 3 + 0], 1.0f);
    int base = blockIdx.x * 1024 + tid;
    for (int it = 0; it < 4; it++) {
        int i = base + it * 256;
        float4 a = boxes[i];
        bool inside = (a.x >= 0.0f) && (a.y >= 0.0f) && (a.z < limw) && (a.w < limh);
        float best = 0.0f; int bidx = 0; bool wm = false;
        if (inside) {
            float aa = f_area(a);
            int cx = min((int)(a.x * (1.0f / 64.0f)), 15);
            int cy = min((int)(a.y * (1.0f / 64.0f)), 15);
            int c = cy * 16 + cx;
            int n = scnt[c];
            const uint8_t* lp = &slist[c * 64];
            for (int j = 0; j < n; j++) {
                int g = lp[j];
                float4 gb = sgt[g];
                float wx = __fadd_rn(__fsub_rn(fminf(a.z, gb.z), fmaxf(a.x, gb.x)), 1.0f);
                float wy = __fadd_rn(__fsub_rn(fminf(a.w, gb.w), fmaxf(a.y, gb.y)), 1.0f);
                wx = fmaxf(wx, 0.0f); wy = fmaxf(wy, 0.0f);
                float inter = __fmul_rn(wx, wy);
                if (inter > 0.0f) {
                    float v = __fdiv_rn(inter, __fsub_rn(__fadd_rn(aa, sga[g]), inter));
                    if (v > best) { best = v; bidx = g; }
                    wm |= (v == sg2af[g]);
                }
            }
        }
        bool pos = inside && (wm || best >= 0.5f);
        bool neg = inside && (best < 0.3f);
        d_aidx[b][i] = (uint8_t)bidx;
        d_lab[b][i] = -1;

        unsigned mneg = __ballot_sync(FULLMASK, neg);
        if (mneg) {
            int leader = __ffs(mneg) - 1, basek = 0;
            if (lane == leader) basek = atomicAdd(&d_negcnt[b], __popc(mneg));
            basek = __shfl_sync(FULLMASK, basek, leader);
            if (neg) d_negl[b][basek + __popc(mneg & ((1u << lane) - 1))] = i;
        }
        unsigned mpos = __ballot_sync(FULLMASK, pos);
        if (mpos) {
            int leader = __ffs(mpos) - 1, basek = 0;
            if (lane == leader) basek = atomicAdd(&d_poscnt[b], __popc(mpos));
            basek = __shfl_sync(FULLMASK, basek, leader);
            if (pos) {
                uint32_t bits = tf_bal(pk0, pk1, pks2,
                                       pks2 + 1u, pk0 + 2u, pk1 + 3u,
                                       pks2 + 4u, pk0 + 5u,
                                       (uint32_t)i + pk1, keys.one,
                                       keys.m13, keys.m17);
                uint32_t m23 = bits >> 9;  // masked low bits shift out anyway
                unsigned long long key =
                    ((unsigned long long)m23 << 18) | (unsigned)(N_ANCH - 1 - i);
                d_poskey[b][basek + __popc(mpos & ((1u << lane) - 1))] = key;
            }
        }
    }
}

// Pass 3: O(P) top-TFG selection via histogram + exact rank in threshold bin.
#define NBIN 4096
#define BINCAP 2048
__global__ __launch_bounds__(1024) void k_select() {
    __shared__ uint32_t hist[NBIN];
    __shared__ unsigned long long binkeys[BINCAP];
    __shared__ int s_thr, s_need, s_cnt;
    int b = blockIdx.x, tid = threadIdx.x;
    int P = d_poscnt[b];
    if (tid == 0) {
        int nf = min(P, TFG);
        int tb = SB - nf;
        d_tbg[b] = tb;
        d_dosamp[b] = (d_negcnt[b] > tb) ? 1 : 0;
    }
    if (P <= TFG) {
        for (int e = tid; e < P; e += 1024) {
            unsigned long long k = d_poskey[b][e];
            d_lab[b][N_ANCH - 1 - (int)(k & 0x3FFFFu)] = 1;
        }
        return;
    }
    for (int i = tid; i < NBIN; i += 1024) hist[i] = 0;
    __syncthreads();
    for (int e = tid; e < P; e += 1024)
        atomicAdd(&hist[(int)(d_poskey[b][e] >> 29)], 1u);
    __syncthreads();
    if (tid == 0) {
        int cum = 0, t = 0, need = TFG;
        for (int bin = NBIN - 1; bin >= 0; bin--) {
            int c = (int)hist[bin];
            if (cum + c >= TFG) { t = bin; need = TFG - cum; break; }
            cum += c;
        }
        s_thr = t; s_need = need; s_cnt = 0;
    }
    __syncthreads();
    int t = s_thr, need = s_need;
    for (int e = tid; e < P; e += 1024) {
        unsigned long long k = d_poskey[b][e];
        int bin = (int)(k >> 29);
        if (bin > t) {
            d_lab[b][N_ANCH - 1 - (int)(k & 0x3FFFFu)] = 1;
        } else if (bin == t) {
            int p = atomicAdd(&s_cnt, 1);
            if (p < BINCAP) binkeys[p] = k;
        }
    }
    __syncthreads();
    int C = min(s_cnt, BINCAP);
    for (int e = tid; e < C; e += 1024) {
        unsigned long long k = binkeys[e];
        int c = 0;
        for (int j = 0; j < C; j++) c += (binkeys[j] > k);
        if (c < need) d_lab[b][N_ANCH - 1 - (int)(k & 0x3FFFFu)] = 1;
    }
}

// Pass 4: categorical sampling. SBT=2 samples per block; pipe-balanced
// threefry; running masked-mantissa max with rare tie branch; exact
// smallest-index tie-break through reductions. Loop structure identical to
// the 1000us champion (R9 lesson: do not restructure).
__global__ __launch_bounds__(256) void k_sample(Keys keys) {
    __shared__ uint32_t redv[SBT][8];
    __shared__ uint32_t redi[SBT][8];
    int b = blockIdx.y, tid = threadIdx.x;
    int s0 = blockIdx.x * SBT;
    int tbg = d_tbg[b];
    if (!d_dosamp[b] || s0 >= tbg) return;
    int M = d_negcnt[b];
    uint32_t one = keys.one, m13 = keys.m13, m17 = keys.m17;
    uint32_t k0 = keys.kn0[b], k1 = keys.kn1[b];
    uint32_t ks2 = k0 ^ k1 ^ 0x1BD11BDAu;
    uint32_t kA = ks2 + 1u, kB = k0 + 2u, kC = k1 + 3u, kD = ks2 + 4u, kE = k0 + 5u;
    uint32_t h0 = (uint32_t)s0 * (uint32_t)N_ANCH + k1;   // x1 base, sample s0
    uint32_t h1 = h0 + (uint32_t)N_ANCH;                  // sample s0+1

    uint32_t bv0 = 0, bi0 = 0xFFFFFFFFu, bv1 = 0, bi1 = 0xFFFFFFFFu;
    const int* negl = d_negl[b];
    for (int t = tid; t < M; t += 256) {
        uint32_t i = (uint32_t)__ldg(&negl[t]);
        uint32_t r0 = tf_bal(k0, k1, ks2, kA, kB, kC, kD, kE, h0 + i, one, m13, m17);
        if (r0 >= bv0) { if (r0 > bv0 || i < bi0) { bv0 = r0; bi0 = i; } }
        uint32_t r1 = tf_bal(k0, k1, ks2, kA, kB, kC, kD, kE, h1 + i, one, m13, m17);
        if (r1 >= bv1) { if (r1 > bv1 || i < bi1) { bv1 = r1; bi1 = i; } }
    }
    int lane = tid & 31, wid = tid >> 5;
    #pragma unroll
    for (int off = 16; off; off >>= 1) {
        uint32_t ov = __shfl_xor_sync(FULLMASK, bv0, off);
        uint32_t oi = __shfl_xor_sync(FULLMASK, bi0, off);
        if (ov > bv0 || (ov == bv0 && oi < bi0)) { bv0 = ov; bi0 = oi; }
        ov = __shfl_xor_sync(FULLMASK, bv1, off);
        oi = __shfl_xor_sync(FULLMASK, bi1, off);
        if (ov > bv1 || (ov == bv1 && oi < bi1)) { bv1 = ov; bi1 = oi; }
    }
    if (lane == 0) {
        redv[0][wid] = bv0; redi[0][wid] = bi0;
        redv[1][wid] = bv1; redi[1][wid] = bi1;
    }
    __syncthreads();
    if (tid < SBT) {
        uint32_t v = redv[tid][0], i = redi[tid][0];
        #pragma unroll
        for (int w = 1; w < 8; w++) {
            uint32_t ov = redv[tid][w], oi = redi[tid][w];
            if (ov > v || (ov == v && oi < i)) { v = ov; i = oi; }
        }
        if (s0 + tid < tbg) d_lab[b][i] = 0;
    }
}

// Pass 5: emit labels (as float) + bbox regression targets.
__global__ __launch_bounds__(256) void k_out(const float4* __restrict__ boxes,
                                             const float4* __restrict__ gt,
                                             float* __restrict__ outL,
                                             float4* __restrict__ outB) {
    __shared__ float4 sgt[NG];
    int b = blockIdx.y, tid = threadIdx.x;
    if (tid < NG) sgt[tid] = gt[b * NG + tid];
    __syncthreads();
    int i = blockIdx.x * 256 + tid;
    int lab = d_lab[b][i];
    outL[b * N_ANCH + i] = (float)lab;
    float4 t = make_float4(0.f, 0.f, 0.f, 0.f);
    if (lab > 0) {
        float4 a = boxes[i];
        float4 g = sgt[d_aidx[b][i]];
        float ew = a.z - a.x + 1.0f, eh = a.w - a.y + 1.0f;
        float ecx = a.x + 0.5f * ew, ecy = a.y + 0.5f * eh;
        float gw = g.z - g.x + 1.0f, gh = g.w - g.y + 1.0f;
        float gcx = g.x + 0.5f * gw, gcy = g.y + 0.5f * gh;
        t.x = (gcx - ecx) / ew;
        t.y = (gcy - ecy) / eh;
        t.z = logf(gw / ew);
        t.w = logf(gh / eh);
    }
    outB[b * N_ANCH + i] = t;
}

// ---------------------------------------------------------------------------
extern "C" void kernel_launch(void* const* d_in, const int* in_sizes, int n_in,
                              void* d_out, int out_size) {
    const float4* boxes = (const float4*)d_in[0];
    const float4* gt    = (const float4*)d_in[1];
    const int*    gti   = (const int*)d_in[3];   // gt_ignore_labels
    const float*  imi   = (const float*)d_in[4]; // im_info
    float* out = (float*)d_out;

    // Host-side key derivation (jax.random.key(42), partitionable threefry).
    Keys keys;
    keys.one = 1u;
    keys.m13 = 1u << 13;
    keys.m17 = 1u << 17;
    for (int b = 0; b < NB; b++) {
        uint32_t kb0, kb1;
        threefry(0u, 42u, 0u, (uint32_t)b, kb0, kb1);         // split(key,B)[b]
        threefry(kb0, kb1, 0u, 0u, keys.kp0[b], keys.kp1[b]); // kp
        threefry(kb0, kb1, 0u, 1u, keys.kn0[b], keys.kn1[b]); // kn
    }

    k_init<<<1, 256>>>();
    k_bins<<<NB, 256>>>(gt, gti);
    k_colmax<<<dim3(N_ANCH / 1024, NB), 256>>>(boxes, gt, imi);
    k_match<<<dim3(N_ANCH / 1024, NB), 256>>>(boxes, gt, imi, keys);
    k_select<<<NB, 1024>>>();
    k_sample<<<dim3(SB / SBT, NB), 256>>>(keys);
    k_out<<<dim3(N_ANCH / 256, NB), 256>>>(boxes, gt, out,
                                           (float4*)(out + NB * N_ANCH));
}

// round 13
// speedup vs baseline: 1.5802x; 1.0238x over previous
#include <cuda_runtime.h>
#include <cstdint>

// ============================================================================
// RPN GT matcher — bit-exact JAX Threefry (partitionable), integer-monotone
// gumbel/uniform ordering, GT spatial binning.
// R11: base = R6 champion (1000us; sampler byte-identical). Low-risk trims:
// k_init merged into k_bins (one fewer launch); k_out vectorized (4 anchors
// per thread, float4 label stores). Sampler untouched — it runs ~88% of its
// alu-pipe floor and all further micro-opts regressed (R7/R8/R9/R10).
// ============================================================================

#define N_ANCH 262144
#define NB 4
#define NG 64
#define TFG 153          // TARGET_FG
#define SB 512           // SAMPLE_BATCH
#define SBT 2            // samples per block in k_sample (empirical optimum)
#define FULLMASK 0xFFFFFFFFu
#define NCELL 256        // 16x16 cells of 64px

struct Keys { uint32_t kp0[NB], kp1[NB], kn0[NB], kn1[NB]; uint32_t one; };

__host__ __device__ __forceinline__ uint32_t rotl32(uint32_t x, int r) {
#ifdef __CUDA_ARCH__
    return __funnelshift_l(x, x, r);
#else
    return (x << r) | (x >> (32 - r));
#endif
}

// Threefry-2x32, 20 rounds, exactly as jax._src.prng.threefry2x32 (host/ref)
__host__ __device__ __forceinline__ void threefry(uint32_t k0, uint32_t k1,
                                                  uint32_t x0, uint32_t x1,
                                                  uint32_t& o0, uint32_t& o1) {
    uint32_t ks2 = k0 ^ k1 ^ 0x1BD11BDAu;
    x0 += k0; x1 += k1;
#define TFR(r) { x0 += x1; x1 = rotl32(x1, r); x1 ^= x0; }
    TFR(13) TFR(15) TFR(26) TFR(6)
    x0 += k1;  x1 += ks2 + 1u;
    TFR(17) TFR(29) TFR(16) TFR(24)
    x0 += ks2; x1 += k0 + 2u;
    TFR(13) TFR(15) TFR(26) TFR(6)
    x0 += k0;  x1 += k1 + 3u;
    TFR(17) TFR(29) TFR(16) TFR(24)
    x0 += k1;  x1 += ks2 + 4u;
    TFR(13) TFR(15) TFR(26) TFR(6)
    x0 += ks2; x1 += k0 + 5u;
#undef TFR
    o0 = x0; o1 = x1;
}

// Threefry with adds expressed as a*one+b (one==1 at runtime, opaque to the
// compiler) so ptxas emits IMAD on the fma pipe instead of IADD3 on the
// saturated alu pipe. x1 must be passed pre-added with k1 (counter x0 = 0).
// Returns o0 ^ o1 (partitionable 32-bit output).
__device__ __forceinline__ uint32_t tf_imad(uint32_t k0, uint32_t k1,
                                            uint32_t ks2,
                                            uint32_t kA, uint32_t kB,
                                            uint32_t kC, uint32_t kD,
                                            uint32_t kE,
                                            uint32_t x1, uint32_t one) {
    uint32_t x0 = k0;
#define AD(a, b) ((a) * one + (b))
#define RR(r) { x0 = AD(x0, x1); x1 = rotl32(x1, (r)); x1 ^= x0; }
    RR(13) RR(15) RR(26) RR(6)
    x0 = AD(x0, k1);  x1 = AD(x1, kA);
    RR(17) RR(29) RR(16) RR(24)
    x0 = AD(x0, ks2); x1 = AD(x1, kB);
    RR(13) RR(15) RR(26) RR(6)
    x0 = AD(x0, k0);  x1 = AD(x1, kC);
    RR(17) RR(29) RR(16) RR(24)
    x0 = AD(x0, k1);  x1 = AD(x1, kD);
    RR(13) RR(15) RR(26) RR(6)
    return AD(x0, ks2) ^ AD(x1, kE);
#undef AD
#undef RR
}

// ---------------------------------------------------------------------------
__device__ __forceinline__ float f_area(float4 v) {
    return __fmul_rn(__fadd_rn(__fsub_rn(v.z, v.x), 1.0f),
                     __fadd_rn(__fsub_rn(v.w, v.y), 1.0f));
}

// ---------------------------------------------------------------------------
// Scratch (static __device__ — no allocation allowed)
// ---------------------------------------------------------------------------
__device__ uint32_t d_g2a[NB][NG];
__device__ uint8_t  d_aidx[NB][N_ANCH];
__device__ int8_t   d_lab[NB][N_ANCH];
__device__ unsigned long long d_poskey[NB][N_ANCH];
__device__ int      d_negl[NB][N_ANCH];
__device__ int      d_poscnt[NB], d_negcnt[NB], d_tbg[NB], d_dosamp[NB];
__device__ __align__(16) uint8_t d_cellgt[NB][NCELL][64];
__device__ int      d_cellcnt[NB][NCELL];

// ---------------------------------------------------------------------------
// Bin valid GTs into 16x16 cells keyed by anchor (x1,y1) position.
// Also performs the (tiny) global init that used to be k_init — writes are
// disjoint and everything is ordered before k_colmax by kernel boundary.
__global__ __launch_bounds__(256) void k_bins(const float4* __restrict__ gt,
                                              const int* __restrict__ gti) {
    int t = blockIdx.x * 256 + threadIdx.x;
    if (blockIdx.x == 0) {
        if (threadIdx.x < NB * NG) ((uint32_t*)d_g2a)[threadIdx.x] = 0;
        if (threadIdx.x < NB) {
            d_poscnt[threadIdx.x] = 0;
            d_negcnt[threadIdx.x] = 0;
        }
    }
    int b = t >> 8, c = t & 255;
    int cx = c & 15, cy = c >> 4;
    float x0 = cx * 64.0f, y0 = cy * 64.0f;
    int n = 0;
    for (int g = 0; g < NG; g++) {
        if (gti[b * NG + g] != 0) continue;
        float4 gb = gt[b * NG + g];
        bool ox = (gb.z >= x0 - 1.5f) && (gb.x <= x0 + 226.5f);
        bool oy = (gb.w >= y0 - 1.5f) && (gb.y <= y0 + 226.5f);
        if (ox && oy) d_cellgt[b][c][n++] = (uint8_t)g;
    }
    d_cellcnt[b][c] = n;
}

// Pass 1: per-gt column max (binned; divide only when inter>0).
__global__ __launch_bounds__(256) void k_colmax(const float4* __restrict__ boxes,
                                                const float4* __restrict__ gt,
                                                const float* __restrict__ imi) {
    __shared__ float4 sgt[NG];
    __shared__ float  sga[NG];
    __shared__ uint32_t sg2a[NG];
    __shared__ uint8_t slist[NCELL * 64];
    __shared__ int     scnt[NCELL];
    int b = blockIdx.y, tid = threadIdx.x;
    if (tid < NG) {
        sg2a[tid] = 0;
        float4 g = gt[b * NG + tid];
        sgt[tid] = g; sga[tid] = f_area(g);
    }
    {
        const int4* src = (const int4*)d_cellgt[b];
        int4* dst = (int4*)slist;
        for (int k = tid; k < NCELL * 64 / 16; k += 256) dst[k] = src[k];
        scnt[tid] = d_cellcnt[b][tid];
    }
    __syncthreads();
    float limw = __fadd_rn(imi[b * 3 + 1], 1.0f);
    float limh = __fadd_rn(imi[b * 3 + 0], 1.0f);
    int base = blockIdx.x * 1024 + tid;
    for (int it = 0; it < 4; it++) {
        int i = base + it * 256;
        float4 a = boxes[i];
        bool inside = (a.x >= 0.0f) && (a.y >= 0.0f) && (a.z < limw) && (a.w < limh);
        if (!inside) continue;
        float aa = f_area(a);
        int cx = min((int)(a.x * (1.0f / 64.0f)), 15);
        int cy = min((int)(a.y * (1.0f / 64.0f)), 15);
        int c = cy * 16 + cx;
        int n = scnt[c];
        const uint8_t* lp = &slist[c * 64];
        for (int j = 0; j < n; j++) {
            int g = lp[j];
            float4 gb = sgt[g];
            float wx = __fadd_rn(__fsub_rn(fminf(a.z, gb.z), fmaxf(a.x, gb.x)), 1.0f);
            float wy = __fadd_rn(__fsub_rn(fminf(a.w, gb.w), fmaxf(a.y, gb.y)), 1.0f);
            wx = fmaxf(wx, 0.0f); wy = fmaxf(wy, 0.0f);
            float inter = __fmul_rn(wx, wy);
            if (inter > 0.0f) {
                float v = __fdiv_rn(inter, __fsub_rn(__fadd_rn(aa, sga[g]), inter));
                atomicMax(&sg2a[g], __float_as_uint(v));
            }
        }
    }
    __syncthreads();
    if (tid < NG && sg2a[tid]) atomicMax(&d_g2a[b][tid], sg2a[tid]);
}

// Pass 2: per-anchor match + classification + compaction + priority keys.
__global__ __launch_bounds__(256) void k_match(const float4* __restrict__ boxes,
                                               const float4* __restrict__ gt,
                                               const float* __restrict__ imi,
                                               Keys keys) {
    __shared__ float4 sgt[NG];
    __shared__ float  sga[NG], sg2af[NG];
    __shared__ uint8_t slist[NCELL * 64];
    __shared__ int     scnt[NCELL];
    int b = blockIdx.y, tid = threadIdx.x, lane = tid & 31;
    if (tid < NG) {
        float4 g = gt[b * NG + tid];
        sgt[tid] = g; sga[tid] = f_area(g);
        float f = __uint_as_float(d_g2a[b][tid]);
        sg2af[tid] = (f == 0.0f) ? 1.0f : f;
    }
    {
        const int4* src = (const int4*)d_cellgt[b];
        int4* dst = (int4*)slist;
        for (int k = tid; k < NCELL * 64 / 16; k += 256) dst[k] = src[k];
        scnt[tid] = d_cellcnt[b][tid];
    }
    __syncthreads();
    uint32_t pk0 = keys.kp0[b], pk1 = keys.kp1[b];
    uint32_t pks2 = pk0 ^ pk1 ^ 0x1BD11BDAu;
    float limw = __fadd_rn(imi[b * 3 + 1], 1.0f);
    float limh = __fadd_rn(imi[b * 3 + 0], 1.0f);
    int base = blockIdx.x * 1024 + tid;
    for (int it = 0; it < 4; it++) {
        int i = base + it * 256;
        float4 a = boxes[i];
        bool inside = (a.x >= 0.0f) && (a.y >= 0.0f) && (a.z < limw) && (a.w < limh);
        float best = 0.0f; int bidx = 0; bool wm = false;
        if (inside) {
            float aa = f_area(a);
            int cx = min((int)(a.x * (1.0f / 64.0f)), 15);
            int cy = min((int)(a.y * (1.0f / 64.0f)), 15);
            int c = cy * 16 + cx;
            int n = scnt[c];
            const uint8_t* lp = &slist[c * 64];
            for (int j = 0; j < n; j++) {
                int g = lp[j];
                float4 gb = sgt[g];
                float wx = __fadd_rn(__fsub_rn(fminf(a.z, gb.z), fmaxf(a.x, gb.x)), 1.0f);
                float wy = __fadd_rn(__fsub_rn(fminf(a.w, gb.w), fmaxf(a.y, gb.y)), 1.0f);
                wx = fmaxf(wx, 0.0f); wy = fmaxf(wy, 0.0f);
                float inter = __fmul_rn(wx, wy);
                if (inter > 0.0f) {
                    float v = __fdiv_rn(inter, __fsub_rn(__fadd_rn(aa, sga[g]), inter));
                    if (v > best) { best = v; bidx = g; }
                    wm |= (v == sg2af[g]);
                }
            }
        }
        bool pos = inside && (wm || best >= 0.5f);
        bool neg = inside && (best < 0.3f);
        d_aidx[b][i] = (uint8_t)bidx;
        d_lab[b][i] = -1;

        unsigned mneg = __ballot_sync(FULLMASK, neg);
        if (mneg) {
            int leader = __ffs(mneg) - 1, basek = 0;
            if (lane == leader) basek = atomicAdd(&d_negcnt[b], __popc(mneg));
            basek = __shfl_sync(FULLMASK, basek, leader);
            if (neg) d_negl[b][basek + __popc(mneg & ((1u << lane) - 1))] = i;
        }
        unsigned mpos = __ballot_sync(FULLMASK, pos);
        if (mpos) {
            int leader = __ffs(mpos) - 1, basek = 0;
            if (lane == leader) basek = atomicAdd(&d_poscnt[b], __popc(mpos));
            basek = __shfl_sync(FULLMASK, basek, leader);
            if (pos) {
                uint32_t bits = tf_imad(pk0, pk1, pks2,
                                        pks2 + 1u, pk0 + 2u, pk1 + 3u,
                                        pks2 + 4u, pk0 + 5u,
                                        (uint32_t)i + pk1, keys.one);
                uint32_t m23 = bits >> 9;
                unsigned long long key =
                    ((unsigned long long)m23 << 18) | (unsigned)(N_ANCH - 1 - i);
                d_poskey[b][basek + __popc(mpos & ((1u << lane) - 1))] = key;
            }
        }
    }
}

// Pass 3: O(P) top-TFG selection via histogram + exact rank in threshold bin.
#define NBIN 4096
#define BINCAP 2048
__global__ __launch_bounds__(1024) void k_select() {
    __shared__ uint32_t hist[NBIN];
    __shared__ unsigned long long binkeys[BINCAP];
    __shared__ int s_thr, s_need, s_cnt;
    int b = blockIdx.x, tid = threadIdx.x;
    int P = d_poscnt[b];
    if (tid == 0) {
        int nf = min(P, TFG);
        int tb = SB - nf;
        d_tbg[b] = tb;
        d_dosamp[b] = (d_negcnt[b] > tb) ? 1 : 0;
    }
    if (P <= TFG) {
        for (int e = tid; e < P; e += 1024) {
            unsigned long long k = d_poskey[b][e];
            d_lab[b][N_ANCH - 1 - (int)(k & 0x3FFFFu)] = 1;
        }
        return;
    }
    for (int i = tid; i < NBIN; i += 1024) hist[i] = 0;
    __syncthreads();
    for (int e = tid; e < P; e += 1024)
        atomicAdd(&hist[(int)(d_poskey[b][e] >> 29)], 1u);
    __syncthreads();
    if (tid == 0) {
        int cum = 0, t = 0, need = TFG;
        for (int bin = NBIN - 1; bin >= 0; bin--) {
            int c = (int)hist[bin];
            if (cum + c >= TFG) { t = bin; need = TFG - cum; break; }
            cum += c;
        }
        s_thr = t; s_need = need; s_cnt = 0;
    }
    __syncthreads();
    int t = s_thr, need = s_need;
    for (int e = tid; e < P; e += 1024) {
        unsigned long long k = d_poskey[b][e];
        int bin = (int)(k >> 29);
        if (bin > t) {
            d_lab[b][N_ANCH - 1 - (int)(k & 0x3FFFFu)] = 1;
        } else if (bin == t) {
            int p = atomicAdd(&s_cnt, 1);
            if (p < BINCAP) binkeys[p] = k;
        }
    }
    __syncthreads();
    int C = min(s_cnt, BINCAP);
    for (int e = tid; e < C; e += 1024) {
        unsigned long long k = binkeys[e];
        int c = 0;
        for (int j = 0; j < C; j++) c += (binkeys[j] > k);
        if (c < need) d_lab[b][N_ANCH - 1 - (int)(k & 0x3FFFFu)] = 1;
    }
}

// Pass 4: categorical sampling — byte-identical to the 1000us champion.
__global__ __launch_bounds__(256) void k_sample(Keys keys) {
    __shared__ uint32_t redv[SBT][8];
    __shared__ uint32_t redi[SBT][8];
    int b = blockIdx.y, tid = threadIdx.x;
    int s0 = blockIdx.x * SBT;
    int tbg = d_tbg[b];
    if (!d_dosamp[b] || s0 >= tbg) return;
    int M = d_negcnt[b];
    uint32_t one = keys.one;
    uint32_t k0 = keys.kn0[b], k1 = keys.kn1[b];
    uint32_t ks2 = k0 ^ k1 ^ 0x1BD11BDAu;
    uint32_t kA = ks2 + 1u, kB = k0 + 2u, kC = k1 + 3u, kD = ks2 + 4u, kE = k0 + 5u;
    uint32_t h0 = (uint32_t)s0 * (uint32_t)N_ANCH + k1;   // x1 base, sample s0
    uint32_t h1 = h0 + (uint32_t)N_ANCH;                  // sample s0+1

    uint32_t bv0 = 0, bi0 = 0xFFFFFFFFu, bv1 = 0, bi1 = 0xFFFFFFFFu;
    const int* negl = d_negl[b];
    for (int t = tid; t < M; t += 256) {
        uint32_t i = (uint32_t)__ldg(&negl[t]);
        uint32_t r0 = tf_imad(k0, k1, ks2, kA, kB, kC, kD, kE, h0 + i, one)
                      & 0xFFFFFE00u;
        if (r0 >= bv0) { if (r0 > bv0 || i < bi0) { bv0 = r0; bi0 = i; } }
        uint32_t r1 = tf_imad(k0, k1, ks2, kA, kB, kC, kD, kE, h1 + i, one)
                      & 0xFFFFFE00u;
        if (r1 >= bv1) { if (r1 > bv1 || i < bi1) { bv1 = r1; bi1 = i; } }
    }
    int lane = tid & 31, wid = tid >> 5;
    #pragma unroll
    for (int off = 16; off; off >>= 1) {
        uint32_t ov = __shfl_xor_sync(FULLMASK, bv0, off);
        uint32_t oi = __shfl_xor_sync(FULLMASK, bi0, off);
        if (ov > bv0 || (ov == bv0 && oi < bi0)) { bv0 = ov; bi0 = oi; }
        ov = __shfl_xor_sync(FULLMASK, bv1, off);
        oi = __shfl_xor_sync(FULLMASK, bi1, off);
        if (ov > bv1 || (ov == bv1 && oi < bi1)) { bv1 = ov; bi1 = oi; }
    }
    if (lane == 0) {
        redv[0][wid] = bv0; redi[0][wid] = bi0;
        redv[1][wid] = bv1; redi[1][wid] = bi1;
    }
    __syncthreads();
    if (tid < SBT) {
        uint32_t v = redv[tid][0], i = redi[tid][0];
        #pragma unroll
        for (int w = 1; w < 8; w++) {
            uint32_t ov = redv[tid][w], oi = redi[tid][w];
            if (ov > v || (ov == v && oi < i)) { v = ov; i = oi; }
        }
        if (s0 + tid < tbg) d_lab[b][i] = 0;
    }
}

// Pass 5: emit labels + bbox regression targets. Vectorized: 4 anchors per
// thread, float4 label stores (16B-aligned since i%4==0).
__global__ __launch_bounds__(256) void k_out(const float4* __restrict__ boxes,
                                             const float4* __restrict__ gt,
                                             float* __restrict__ outL,
                                             float4* __restrict__ outB) {
    __shared__ float4 sgt[NG];
    int b = blockIdx.y, tid = threadIdx.x;
    if (tid < NG) sgt[tid] = gt[b * NG + tid];
    __syncthreads();
    int i0 = (blockIdx.x * 256 + tid) * 4;
    // labels: packed 4-at-a-time
    char4 l4 = *(const char4*)&d_lab[b][i0];
    int labs[4] = { l4.x, l4.y, l4.z, l4.w };
    float4 lv = make_float4((float)labs[0], (float)labs[1],
                            (float)labs[2], (float)labs[3]);
    *(float4*)&outL[b * N_ANCH + i0] = lv;
    float4* outb = &outB[b * N_ANCH + i0];
    #pragma unroll
    for (int u = 0; u < 4; u++) {
        float4 t = make_float4(0.f, 0.f, 0.f, 0.f);
        if (labs[u] > 0) {
            int i = i0 + u;
            float4 a = boxes[i];
            float4 g = sgt[d_aidx[b][i]];
            float ew = a.z - a.x + 1.0f, eh = a.w - a.y + 1.0f;
            float ecx = a.x + 0.5f * ew, ecy = a.y + 0.5f * eh;
            float gw = g.z - g.x + 1.0f, gh = g.w - g.y + 1.0f;
            float gcx = g.x + 0.5f * gw, gcy = g.y + 0.5f * gh;
            t.x = (gcx - ecx) / ew;
            t.y = (gcy - ecy) / eh;
            t.z = logf(gw / ew);
            t.w = logf(gh / eh);
        }
        outb[u] = t;
    }
}

// ---------------------------------------------------------------------------
extern "C" void kernel_launch(void* const* d_in, const int* in_sizes, int n_in,
                              void* d_out, int out_size) {
    const float4* boxes = (const float4*)d_in[0];
    const float4* gt    = (const float4*)d_in[1];
    const int*    gti   = (const int*)d_in[3];   // gt_ignore_labels
    const float*  imi   = (const float*)d_in[4]; // im_info
    float* out = (float*)d_out;

    // Host-side key derivation (jax.random.key(42), partitionable threefry).
    Keys keys;
    keys.one = 1u;
    for (int b = 0; b < NB; b++) {
        uint32_t kb0, kb1;
        threefry(0u, 42u, 0u, (uint32_t)b, kb0, kb1);         // split(key,B)[b]
        threefry(kb0, kb1, 0u, 0u, keys.kp0[b], keys.kp1[b]); // kp
        threefry(kb0, kb1, 0u, 1u, keys.kn0[b], keys.kn1[b]); // kn
    }

    k_bins<<<NB, 256>>>(gt, gti);
    k_colmax<<<dim3(N_ANCH / 1024, NB), 256>>>(boxes, gt, imi);
    k_match<<<dim3(N_ANCH / 1024, NB), 256>>>(boxes, gt, imi, keys);
    k_select<<<NB, 1024>>>();
    k_sample<<<dim3(SB / SBT, NB), 256>>>(keys);
    k_out<<<dim3(N_ANCH / 1024, NB), 256>>>(boxes, gt, out,
                                            (float4*)(out + NB * N_ANCH));
}

// round 14
// speedup vs baseline: 2.0034x; 1.2678x over previous
#include <cuda_runtime.h>
#include <cstdint>

// ============================================================================
// RPN GT matcher — bit-exact JAX Threefry (partitionable), integer-monotone
// gumbel/uniform ordering, GT spatial binning.
// R13: sampler wave-quantization fix. k_sample blocks now cover (sample-pair,
// M-chunk) with NCHUNK=4 — short blocks stream through the ~888-block wave
// capacity with a ~2% tail instead of ~74%. Partial maxima merge via global
// atomicMax on packed (bits<<32)|(N_ANCH-i) (same value-then-min-index
// order); k_resolve scatters winners. Inner loop body byte-identical.
// ============================================================================

#define N_ANCH 262144
#define NB 4
#define NG 64
#define TFG 153          // TARGET_FG
#define SB 512           // SAMPLE_BATCH
#define SBT 2            // samples per block-pair (empirical optimum)
#define NCHUNK 4         // M-chunks per sample-pair
#define FULLMASK 0xFFFFFFFFu
#define NCELL 256        // 16x16 cells of 64px

struct Keys { uint32_t kp0[NB], kp1[NB], kn0[NB], kn1[NB]; uint32_t one; };

__host__ __device__ __forceinline__ uint32_t rotl32(uint32_t x, int r) {
#ifdef __CUDA_ARCH__
    return __funnelshift_l(x, x, r);
#else
    return (x << r) | (x >> (32 - r));
#endif
}

// Threefry-2x32, 20 rounds, exactly as jax._src.prng.threefry2x32 (host/ref)
__host__ __device__ __forceinline__ void threefry(uint32_t k0, uint32_t k1,
                                                  uint32_t x0, uint32_t x1,
                                                  uint32_t& o0, uint32_t& o1) {
    uint32_t ks2 = k0 ^ k1 ^ 0x1BD11BDAu;
    x0 += k0; x1 += k1;
#define TFR(r) { x0 += x1; x1 = rotl32(x1, r); x1 ^= x0; }
    TFR(13) TFR(15) TFR(26) TFR(6)
    x0 += k1;  x1 += ks2 + 1u;
    TFR(17) TFR(29) TFR(16) TFR(24)
    x0 += ks2; x1 += k0 + 2u;
    TFR(13) TFR(15) TFR(26) TFR(6)
    x0 += k0;  x1 += k1 + 3u;
    TFR(17) TFR(29) TFR(16) TFR(24)
    x0 += k1;  x1 += ks2 + 4u;
    TFR(13) TFR(15) TFR(26) TFR(6)
    x0 += ks2; x1 += k0 + 5u;
#undef TFR
    o0 = x0; o1 = x1;
}

// Threefry with adds expressed as a*one+b (one==1 at runtime, opaque to the
// compiler) so ptxas emits IMAD on the fma pipe instead of IADD3 on the
// saturated alu pipe. x1 must be passed pre-added with k1 (counter x0 = 0).
// Returns o0 ^ o1 (partitionable 32-bit output).
__device__ __forceinline__ uint32_t tf_imad(uint32_t k0, uint32_t k1,
                                            uint32_t ks2,
                                            uint32_t kA, uint32_t kB,
                                            uint32_t kC, uint32_t kD,
                                            uint32_t kE,
                                            uint32_t x1, uint32_t one) {
    uint32_t x0 = k0;
#define AD(a, b) ((a) * one + (b))
#define RR(r) { x0 = AD(x0, x1); x1 = rotl32(x1, (r)); x1 ^= x0; }
    RR(13) RR(15) RR(26) RR(6)
    x0 = AD(x0, k1);  x1 = AD(x1, kA);
    RR(17) RR(29) RR(16) RR(24)
    x0 = AD(x0, ks2); x1 = AD(x1, kB);
    RR(13) RR(15) RR(26) RR(6)
    x0 = AD(x0, k0);  x1 = AD(x1, kC);
    RR(17) RR(29) RR(16) RR(24)
    x0 = AD(x0, k1);  x1 = AD(x1, kD);
    RR(13) RR(15) RR(26) RR(6)
    return AD(x0, ks2) ^ AD(x1, kE);
#undef AD
#undef RR
}

// ---------------------------------------------------------------------------
__device__ __forceinline__ float f_area(float4 v) {
    return __fmul_rn(__fadd_rn(__fsub_rn(v.z, v.x), 1.0f),
                     __fadd_rn(__fsub_rn(v.w, v.y), 1.0f));
}

// ---------------------------------------------------------------------------
// Scratch (static __device__ — no allocation allowed)
// ---------------------------------------------------------------------------
__device__ uint32_t d_g2a[NB][NG];
__device__ uint8_t  d_aidx[NB][N_ANCH];
__device__ int8_t   d_lab[NB][N_ANCH];
__device__ unsigned long long d_poskey[NB][N_ANCH];
__device__ int      d_negl[NB][N_ANCH];
__device__ int      d_poscnt[NB], d_negcnt[NB], d_tbg[NB], d_dosamp[NB];
__device__ __align__(16) uint8_t d_cellgt[NB][NCELL][64];
__device__ int      d_cellcnt[NB][NCELL];
__device__ unsigned long long d_samp[NB][SB];   // packed (bits<<32)|(N-i)

// ---------------------------------------------------------------------------
// Bin valid GTs into cells; also init counters and d_samp slots.
__global__ __launch_bounds__(256) void k_bins(const float4* __restrict__ gt,
                                              const int* __restrict__ gti) {
    int tid = threadIdx.x;
    int b = blockIdx.x, c = tid;
    if (b == 0) {
        if (tid < NB * NG) ((uint32_t*)d_g2a)[tid] = 0;
        if (tid < NB) { d_poscnt[tid] = 0; d_negcnt[tid] = 0; }
    }
    d_samp[b][tid] = 0ull;
    d_samp[b][tid + 256] = 0ull;
    int cx = c & 15, cy = c >> 4;
    float x0 = cx * 64.0f, y0 = cy * 64.0f;
    int n = 0;
    for (int g = 0; g < NG; g++) {
        if (gti[b * NG + g] != 0) continue;
        float4 gb = gt[b * NG + g];
        bool ox = (gb.z >= x0 - 1.5f) && (gb.x <= x0 + 226.5f);
        bool oy = (gb.w >= y0 - 1.5f) && (gb.y <= y0 + 226.5f);
        if (ox && oy) d_cellgt[b][c][n++] = (uint8_t)g;
    }
    d_cellcnt[b][c] = n;
}

// Pass 1: per-gt column max (binned; divide only when inter>0).
__global__ __launch_bounds__(256) void k_colmax(const float4* __restrict__ boxes,
                                                const float4* __restrict__ gt,
                                                const float* __restrict__ imi) {
    __shared__ float4 sgt[NG];
    __shared__ float  sga[NG];
    __shared__ uint32_t sg2a[NG];
    __shared__ uint8_t slist[NCELL * 64];
    __shared__ int     scnt[NCELL];
    int b = blockIdx.y, tid = threadIdx.x;
    if (tid < NG) {
        sg2a[tid] = 0;
        float4 g = gt[b * NG + tid];
        sgt[tid] = g; sga[tid] = f_area(g);
    }
    {
        const int4* src = (const int4*)d_cellgt[b];
        int4* dst = (int4*)slist;
        for (int k = tid; k < NCELL * 64 / 16; k += 256) dst[k] = src[k];
        scnt[tid] = d_cellcnt[b][tid];
    }
    __syncthreads();
    float limw = __fadd_rn(imi[b * 3 + 1], 1.0f);
    float limh = __fadd_rn(imi[b * 3 + 0], 1.0f);
    int base = blockIdx.x * 1024 + tid;
    for (int it = 0; it < 4; it++) {
        int i = base + it * 256;
        float4 a = boxes[i];
        bool inside = (a.x >= 0.0f) && (a.y >= 0.0f) && (a.z < limw) && (a.w < limh);
        if (!inside) continue;
        float aa = f_area(a);
        int cx = min((int)(a.x * (1.0f / 64.0f)), 15);
        int cy = min((int)(a.y * (1.0f / 64.0f)), 15);
        int c = cy * 16 + cx;
        int n = scnt[c];
        const uint8_t* lp = &slist[c * 64];
        for (int j = 0; j < n; j++) {
            int g = lp[j];
            float4 gb = sgt[g];
            float wx = __fadd_rn(__fsub_rn(fminf(a.z, gb.z), fmaxf(a.x, gb.x)), 1.0f);
            float wy = __fadd_rn(__fsub_rn(fminf(a.w, gb.w), fmaxf(a.y, gb.y)), 1.0f);
            wx = fmaxf(wx, 0.0f); wy = fmaxf(wy, 0.0f);
            float inter = __fmul_rn(wx, wy);
            if (inter > 0.0f) {
                float v = __fdiv_rn(inter, __fsub_rn(__fadd_rn(aa, sga[g]), inter));
                atomicMax(&sg2a[g], __float_as_uint(v));
            }
        }
    }
    __syncthreads();
    if (tid < NG && sg2a[tid]) atomicMax(&d_g2a[b][tid], sg2a[tid]);
}

// Pass 2: per-anchor match + classification + compaction + priority keys.
__global__ __launch_bounds__(256) void k_match(const float4* __restrict__ boxes,
                                               const float4* __restrict__ gt,
                                               const float* __restrict__ imi,
                                               Keys keys) {
    __shared__ float4 sgt[NG];
    __shared__ float  sga[NG], sg2af[NG];
    __shared__ uint8_t slist[NCELL * 64];
    __shared__ int     scnt[NCELL];
    int b = blockIdx.y, tid = threadIdx.x, lane = tid & 31;
    if (tid < NG) {
        float4 g = gt[b * NG + tid];
        sgt[tid] = g; sga[tid] = f_area(g);
        float f = __uint_as_float(d_g2a[b][tid]);
        sg2af[tid] = (f == 0.0f) ? 1.0f : f;
    }
    {
        const int4* src = (const int4*)d_cellgt[b];
        int4* dst = (int4*)slist;
        for (int k = tid; k < NCELL * 64 / 16; k += 256) dst[k] = src[k];
        scnt[tid] = d_cellcnt[b][tid];
    }
    __syncthreads();
    uint32_t pk0 = keys.kp0[b], pk1 = keys.kp1[b];
    uint32_t pks2 = pk0 ^ pk1 ^ 0x1BD11BDAu;
    float limw = __fadd_rn(imi[b * 3 + 1], 1.0f);
    float limh = __fadd_rn(imi[b * 3 + 0], 1.0f);
    int base = blockIdx.x * 1024 + tid;
    for (int it = 0; it < 4; it++) {
        int i = base + it * 256;
        float4 a = boxes[i];
        bool inside = (a.x >= 0.0f) && (a.y >= 0.0f) && (a.z < limw) && (a.w < limh);
        float best = 0.0f; int bidx = 0; bool wm = false;
        if (inside) {
            float aa = f_area(a);
            int cx = min((int)(a.x * (1.0f / 64.0f)), 15);
            int cy = min((int)(a.y * (1.0f / 64.0f)), 15);
            int c = cy * 16 + cx;
            int n = scnt[c];
            const uint8_t* lp = &slist[c * 64];
            for (int j = 0; j < n; j++) {
                int g = lp[j];
                float4 gb = sgt[g];
                float wx = __fadd_rn(__fsub_rn(fminf(a.z, gb.z), fmaxf(a.x, gb.x)), 1.0f);
                float wy = __fadd_rn(__fsub_rn(fminf(a.w, gb.w), fmaxf(a.y, gb.y)), 1.0f);
                wx = fmaxf(wx, 0.0f); wy = fmaxf(wy, 0.0f);
                float inter = __fmul_rn(wx, wy);
                if (inter > 0.0f) {
                    float v = __fdiv_rn(inter, __fsub_rn(__fadd_rn(aa, sga[g]), inter));
                    if (v > best) { best = v; bidx = g; }
                    wm |= (v == sg2af[g]);
                }
            }
        }
        bool pos = inside && (wm || best >= 0.5f);
        bool neg = inside && (best < 0.3f);
        d_aidx[b][i] = (uint8_t)bidx;
        d_lab[b][i] = -1;

        unsigned mneg = __ballot_sync(FULLMASK, neg);
        if (mneg) {
            int leader = __ffs(mneg) - 1, basek = 0;
            if (lane == leader) basek = atomicAdd(&d_negcnt[b], __popc(mneg));
            basek = __shfl_sync(FULLMASK, basek, leader);
            if (neg) d_negl[b][basek + __popc(mneg & ((1u << lane) - 1))] = i;
        }
        unsigned mpos = __ballot_sync(FULLMASK, pos);
        if (mpos) {
            int leader = __ffs(mpos) - 1, basek = 0;
            if (lane == leader) basek = atomicAdd(&d_poscnt[b], __popc(mpos));
            basek = __shfl_sync(FULLMASK, basek, leader);
            if (pos) {
                uint32_t bits = tf_imad(pk0, pk1, pks2,
                                        pks2 + 1u, pk0 + 2u, pk1 + 3u,
                                        pks2 + 4u, pk0 + 5u,
                                        (uint32_t)i + pk1, keys.one);
                uint32_t m23 = bits >> 9;
                unsigned long long key =
                    ((unsigned long long)m23 << 18) | (unsigned)(N_ANCH - 1 - i);
                d_poskey[b][basek + __popc(mpos & ((1u << lane) - 1))] = key;
            }
        }
    }
}

// Pass 3: O(P) top-TFG selection via histogram + exact rank in threshold bin.
#define NBIN 4096
#define BINCAP 2048
__global__ __launch_bounds__(1024) void k_select() {
    __shared__ uint32_t hist[NBIN];
    __shared__ unsigned long long binkeys[BINCAP];
    __shared__ int s_thr, s_need, s_cnt;
    int b = blockIdx.x, tid = threadIdx.x;
    int P = d_poscnt[b];
    if (tid == 0) {
        int nf = min(P, TFG);
        int tb = SB - nf;
        d_tbg[b] = tb;
        d_dosamp[b] = (d_negcnt[b] > tb) ? 1 : 0;
    }
    if (P <= TFG) {
        for (int e = tid; e < P; e += 1024) {
            unsigned long long k = d_poskey[b][e];
            d_lab[b][N_ANCH - 1 - (int)(k & 0x3FFFFu)] = 1;
        }
        return;
    }
    for (int i = tid; i < NBIN; i += 1024) hist[i] = 0;
    __syncthreads();
    for (int e = tid; e < P; e += 1024)
        atomicAdd(&hist[(int)(d_poskey[b][e] >> 29)], 1u);
    __syncthreads();
    if (tid == 0) {
        int cum = 0, t = 0, need = TFG;
        for (int bin = NBIN - 1; bin >= 0; bin--) {
            int c = (int)hist[bin];
            if (cum + c >= TFG) { t = bin; need = TFG - cum; break; }
            cum += c;
        }
        s_thr = t; s_need = need; s_cnt = 0;
    }
    __syncthreads();
    int t = s_thr, need = s_need;
    for (int e = tid; e < P; e += 1024) {
        unsigned long long k = d_poskey[b][e];
        int bin = (int)(k >> 29);
        if (bin > t) {
            d_lab[b][N_ANCH - 1 - (int)(k & 0x3FFFFu)] = 1;
        } else if (bin == t) {
            int p = atomicAdd(&s_cnt, 1);
            if (p < BINCAP) binkeys[p] = k;
        }
    }
    __syncthreads();
    int C = min(s_cnt, BINCAP);
    for (int e = tid; e < C; e += 1024) {
        unsigned long long k = binkeys[e];
        int c = 0;
        for (int j = 0; j < C; j++) c += (binkeys[j] > k);
        if (c < need) d_lab[b][N_ANCH - 1 - (int)(k & 0x3FFFFu)] = 1;
    }
}

// Pass 4: categorical sampling. Block = (sample-pair, M-chunk). Inner loop
// body byte-identical to champion; only bounds differ. Block-local max
// merges into d_samp via u64 atomicMax: (bits<<32)|(N_ANCH-i) orders by
// value then by smallest index (low tag >= 1, init 0; empty partials skip).
__global__ __launch_bounds__(256) void k_sample(Keys keys) {
    __shared__ uint32_t redv[SBT][8];
    __shared__ uint32_t redi[SBT][8];
    int b = blockIdx.y, tid = threadIdx.x;
    int pair = blockIdx.x >> 2;           // NCHUNK == 4
    int chunk = blockIdx.x & 3;
    int s0 = pair * SBT;
    int tbg = d_tbg[b];
    if (!d_dosamp[b] || s0 >= tbg) return;
    int M = d_negcnt[b];
    int clen = (M + NCHUNK - 1) / NCHUNK;
    int start = chunk * clen;
    int end = min(start + clen, M);
    uint32_t one = keys.one;
    uint32_t k0 = keys.kn0[b], k1 = keys.kn1[b];
    uint32_t ks2 = k0 ^ k1 ^ 0x1BD11BDAu;
    uint32_t kA = ks2 + 1u, kB = k0 + 2u, kC = k1 + 3u, kD = ks2 + 4u, kE = k0 + 5u;
    uint32_t h0 = (uint32_t)s0 * (uint32_t)N_ANCH + k1;   // x1 base, sample s0
    uint32_t h1 = h0 + (uint32_t)N_ANCH;                  // sample s0+1

    uint32_t bv0 = 0, bi0 = 0xFFFFFFFFu, bv1 = 0, bi1 = 0xFFFFFFFFu;
    const int* negl = d_negl[b];
    for (int t = start + tid; t < end; t += 256) {
        uint32_t i = (uint32_t)__ldg(&negl[t]);
        uint32_t r0 = tf_imad(k0, k1, ks2, kA, kB, kC, kD, kE, h0 + i, one)
                      & 0xFFFFFE00u;
        if (r0 >= bv0) { if (r0 > bv0 || i < bi0) { bv0 = r0; bi0 = i; } }
        uint32_t r1 = tf_imad(k0, k1, ks2, kA, kB, kC, kD, kE, h1 + i, one)
                      & 0xFFFFFE00u;
        if (r1 >= bv1) { if (r1 > bv1 || i < bi1) { bv1 = r1; bi1 = i; } }
    }
    int lane = tid & 31, wid = tid >> 5;
    #pragma unroll
    for (int off = 16; off; off >>= 1) {
        uint32_t ov = __shfl_xor_sync(FULLMASK, bv0, off);
        uint32_t oi = __shfl_xor_sync(FULLMASK, bi0, off);
        if (ov > bv0 || (ov == bv0 && oi < bi0)) { bv0 = ov; bi0 = oi; }
        ov = __shfl_xor_sync(FULLMASK, bv1, off);
        oi = __shfl_xor_sync(FULLMASK, bi1, off);
        if (ov > bv1 || (ov == bv1 && oi < bi1)) { bv1 = ov; bi1 = oi; }
    }
    if (lane == 0) {
        redv[0][wid] = bv0; redi[0][wid] = bi0;
        redv[1][wid] = bv1; redi[1][wid] = bi1;
    }
    __syncthreads();
    if (tid < SBT) {
        uint32_t v = redv[tid][0], i = redi[tid][0];
        #pragma unroll
        for (int w = 1; w < 8; w++) {
            uint32_t ov = redv[tid][w], oi = redi[tid][w];
            if (ov > v || (ov == v && oi < i)) { v = ov; i = oi; }
        }
        if (s0 + tid < tbg && i != 0xFFFFFFFFu) {
            unsigned long long pk =
                ((unsigned long long)v << 32) | (uint32_t)(N_ANCH - i);
            atomicMax(&d_samp[b][s0 + tid], pk);
        }
    }
}

// Pass 4b: scatter resolved sample winners into labels.
__global__ __launch_bounds__(256) void k_resolve() {
    int b = blockIdx.x, tid = threadIdx.x;
    int tbg = d_tbg[b];
    for (int s = tid; s < tbg; s += 256) {
        unsigned long long p = d_samp[b][s];
        if (p) d_lab[b][N_ANCH - (uint32_t)p] = 0;
    }
}

// Pass 5: emit labels + bbox regression targets (vectorized, 4/thread).
__global__ __launch_bounds__(256) void k_out(const float4* __restrict__ boxes,
                                             const float4* __restrict__ gt,
                                             float* __restrict__ outL,
                                             float4* __restrict__ outB) {
    __shared__ float4 sgt[NG];
    int b = blockIdx.y, tid = threadIdx.x;
    if (tid < NG) sgt[tid] = gt[b * NG + tid];
    __syncthreads();
    int i0 = (blockIdx.x * 256 + tid) * 4;
    char4 l4 = *(const char4*)&d_lab[b][i0];
    int labs[4] = { l4.x, l4.y, l4.z, l4.w };
    float4 lv = make_float4((float)labs[0], (float)labs[1],
                            (float)labs[2], (float)labs[3]);
    *(float4*)&outL[b * N_ANCH + i0] = lv;
    float4* outb = &outB[b * N_ANCH + i0];
    #pragma unroll
    for (int u = 0; u < 4; u++) {
        float4 t = make_float4(0.f, 0.f, 0.f, 0.f);
        if (labs[u] > 0) {
            int i = i0 + u;
            float4 a = boxes[i];
            float4 g = sgt[d_aidx[b][i]];
            float ew = a.z - a.x + 1.0f, eh = a.w - a.y + 1.0f;
            float ecx = a.x + 0.5f * ew, ecy = a.y + 0.5f * eh;
            float gw = g.z - g.x + 1.0f, gh = g.w - g.y + 1.0f;
            float gcx = g.x + 0.5f * gw, gcy = g.y + 0.5f * gh;
            t.x = (gcx - ecx) / ew;
            t.y = (gcy - ecy) / eh;
            t.z = logf(gw / ew);
            t.w = logf(gh / eh);
        }
        outb[u] = t;
    }
}

// ---------------------------------------------------------------------------
extern "C" void kernel_launch(void* const* d_in, const int* in_sizes, int n_in,
                              void* d_out, int out_size) {
    const float4* boxes = (const float4*)d_in[0];
    const float4* gt    = (const float4*)d_in[1];
    const int*    gti   = (const int*)d_in[3];   // gt_ignore_labels
    const float*  imi   = (const float*)d_in[4]; // im_info
    float* out = (float*)d_out;

    // Host-side key derivation (jax.random.key(42), partitionable threefry).
    Keys keys;
    keys.one = 1u;
    for (int b = 0; b < NB; b++) {
        uint32_t kb0, kb1;
        threefry(0u, 42u, 0u, (uint32_t)b, kb0, kb1);         // split(key,B)[b]
        threefry(kb0, kb1, 0u, 0u, keys.kp0[b], keys.kp1[b]); // kp
        threefry(kb0, kb1, 0u, 1u, keys.kn0[b], keys.kn1[b]); // kn
    }

    k_bins<<<NB, 256>>>(gt, gti);
    k_colmax<<<dim3(N_ANCH / 1024, NB), 256>>>(boxes, gt, imi);
    k_match<<<dim3(N_ANCH / 1024, NB), 256>>>(boxes, gt, imi, keys);
    k_select<<<NB, 1024>>>();
    k_sample<<<dim3((SB / SBT) * NCHUNK, NB), 256>>>(keys);
    k_resolve<<<NB, 256>>>();
    k_out<<<dim3(N_ANCH / 1024, NB), 256>>>(boxes, gt, out,
                                            (float4*)(out + NB * N_ANCH));
}